// round 7
// baseline (speedup 1.0000x reference)
#include <cuda_runtime.h>
#include <cuda_fp16.h>

#define VOCAB 10000
#define EMBED 300
#define BATCH 262144

#define ROW_H2 160                                  // padded row stride in half2 (320 halves)
#define H2_PER_ROW 150                              // real half2 per row

#define NBLOCKS 2048
#define NTHREADS 256
#define GROUPS_PER_BLOCK (NTHREADS / 4)             // 64 four-lane groups
#define TOTAL_GROUPS (NBLOCKS * GROUPS_PER_BLOCK)   // 131072
#define PAIRS_PER_GROUP (BATCH / TOTAL_GROUPS)      // 2

// fp16 copies of V and U (zero-initialized at load; pad columns 150..159 never
// written -> contribute nothing to the dots).
__device__ __half2       g_Vh[VOCAB * ROW_H2];
__device__ __half2       g_Uh[VOCAB * ROW_H2];
__device__ float         g_partials[NBLOCKS];
__device__ unsigned int  g_count = 0;               // self-resets each run

// ---------------- Pass 1: fp32 -> fp16 conversion (streaming) ----------------
__global__ void glove_conv_kernel(const float* __restrict__ V,
                                  const float* __restrict__ U) {
    const int PER = VOCAB * H2_PER_ROW;             // 1.5M half2 per matrix
    int t = blockIdx.x * blockDim.x + threadIdx.x;
    if (t < PER) {
        int row = t / H2_PER_ROW;
        int c   = t - row * H2_PER_ROW;
        float2 f = ((const float2*)(V + (size_t)row * EMBED))[c];
        g_Vh[row * ROW_H2 + c] = __floats2half2_rn(f.x, f.y);
    } else if (t < 2 * PER) {
        int s   = t - PER;
        int row = s / H2_PER_ROW;
        int c   = s - row * H2_PER_ROW;
        float2 f = ((const float2*)(U + (size_t)row * EMBED))[c];
        g_Uh[row * ROW_H2 + c] = __floats2half2_rn(f.x, f.y);
    }
}

// ---------------- Pass 2: fused gather + dot + loss + reduce ----------------
__global__ void __launch_bounds__(NTHREADS)
glove_main_kernel(const int* __restrict__ ci,
                  const int* __restrict__ cj,
                  const float* __restrict__ vb,
                  const float* __restrict__ ub,
                  const float* __restrict__ comat,
                  float* __restrict__ out) {
    const int lane = threadIdx.x & 31;
    const int sub  = lane & 3;                      // lane within 4-lane group
    const int wid  = threadIdx.x >> 5;
    const int group = blockIdx.x * GROUPS_PER_BLOCK + (threadIdx.x >> 2);

    // Hoist both pairs' indices: overlap index-load latency with everything.
    const int p0 = group;
    const int p1 = group + TOTAL_GROUPS;
    const int i0 = ci[p0], j0 = cj[p0];
    const int i1 = ci[p1], j1 = cj[p1];

    float gsum = 0.0f;                              // only sub==0 lanes accumulate

    #pragma unroll
    for (int q = 0; q < PAIRS_PER_GROUP; q++) {
        const int i = q ? i1 : i0;
        const int j = q ? j1 : j0;

        const uint4* __restrict__ v4 = (const uint4*)(g_Vh + (size_t)i * ROW_H2);
        const uint4* __restrict__ u4 = (const uint4*)(g_Uh + (size_t)j * ROW_H2);

        // 40 uint4 (=320 halves incl. zero pad) per row; 4 lanes x 10 rounds.
        // Two accumulators to halve the FMA dependency chain.
        float acc0 = 0.0f, acc1 = 0.0f;
        #pragma unroll
        for (int k = 0; k < 10; k++) {
            uint4 a = v4[sub + k * 4];
            uint4 b = u4[sub + k * 4];
            const __half2* ah = (const __half2*)&a;
            const __half2* bh = (const __half2*)&b;
            float2 a0 = __half22float2(ah[0]), b0 = __half22float2(bh[0]);
            float2 a1 = __half22float2(ah[1]), b1 = __half22float2(bh[1]);
            float2 a2 = __half22float2(ah[2]), b2 = __half22float2(bh[2]);
            float2 a3 = __half22float2(ah[3]), b3 = __half22float2(bh[3]);
            acc0 = fmaf(a0.x, b0.x, acc0); acc1 = fmaf(a0.y, b0.y, acc1);
            acc0 = fmaf(a1.x, b1.x, acc0); acc1 = fmaf(a1.y, b1.y, acc1);
            acc0 = fmaf(a2.x, b2.x, acc0); acc1 = fmaf(a2.y, b2.y, acc1);
            acc0 = fmaf(a3.x, b3.x, acc0); acc1 = fmaf(a3.y, b3.y, acc1);
        }
        float acc = acc0 + acc1;

        // reduce within the 4-lane group (2 shfls)
        acc += __shfl_xor_sync(0xffffffffu, acc, 2);
        acc += __shfl_xor_sync(0xffffffffu, acc, 1);

        if (sub == 0) {
            float x = __ldg(comat + (size_t)i * VOCAB + j);
            float w = (x < 100.0f) ? __powf(x * 0.01f, 0.75f) : 1.0f;
            float r = acc + __ldg(vb + i) + __ldg(ub + j) - __logf(x);
            gsum += w * r * r;
        }
    }

    // warp reduce: nonzero only on lanes 0,4,8,...,28
    gsum += __shfl_xor_sync(0xffffffffu, gsum, 4);
    gsum += __shfl_xor_sync(0xffffffffu, gsum, 8);
    gsum += __shfl_xor_sync(0xffffffffu, gsum, 16);

    __shared__ float swsum[NTHREADS / 32];
    __shared__ bool  s_last;
    if (lane == 0) swsum[wid] = gsum;
    __syncthreads();

    if (threadIdx.x == 0) {
        float bsum = 0.0f;
        #pragma unroll
        for (int w = 0; w < NTHREADS / 32; w++) bsum += swsum[w];
        g_partials[blockIdx.x] = bsum;
        __threadfence();
        unsigned int t = atomicAdd(&g_count, 1u);
        s_last = (t == (unsigned int)(gridDim.x - 1));
    }
    __syncthreads();

    if (s_last) {
        double d = 0.0;
        for (int k = threadIdx.x; k < NBLOCKS; k += NTHREADS)
            d += (double)g_partials[k];
        #pragma unroll
        for (int off = 16; off; off >>= 1)
            d += __shfl_xor_sync(0xffffffffu, d, off);

        __shared__ double sdw[NTHREADS / 32];
        if (lane == 0) sdw[wid] = d;
        __syncthreads();
        if (threadIdx.x == 0) {
            double total = 0.0;
            #pragma unroll
            for (int w = 0; w < NTHREADS / 32; w++) total += sdw[w];
            out[0] = (float)total;
            g_count = 0;                            // reset for next graph replay
        }
    }
}

extern "C" void kernel_launch(void* const* d_in, const int* in_sizes, int n_in,
                              void* d_out, int out_size) {
    const int*   ci    = (const int*)d_in[0];
    const int*   cj    = (const int*)d_in[1];
    const float* V     = (const float*)d_in[2];
    const float* U     = (const float*)d_in[3];
    const float* vb    = (const float*)d_in[4];
    const float* ub    = (const float*)d_in[5];
    const float* comat = (const float*)d_in[6];
    float* out = (float*)d_out;

    const int conv_items = 2 * VOCAB * H2_PER_ROW;  // 3M half2 writes
    glove_conv_kernel<<<(conv_items + 255) / 256, 256>>>(V, U);
    glove_main_kernel<<<NBLOCKS, NTHREADS>>>(ci, cj, vb, ub, comat, out);
}

// round 8
// speedup vs baseline: 1.2289x; 1.2289x over previous
#include <cuda_runtime.h>
#include <cuda_fp16.h>

#define VOCAB 10000
#define EMBED 300
#define BATCH 262144

#define ROW_H2 160                                  // padded row stride in half2 (320 halves)
#define H2_PER_ROW 150                              // real half2 per row

#define NBLOCKS 2048
#define NTHREADS 256
#define GROUPS_PER_BLOCK (NTHREADS / 8)             // 32 eight-lane groups
#define TOTAL_GROUPS (NBLOCKS * GROUPS_PER_BLOCK)   // 65536
#define PAIRS_PER_GROUP (BATCH / TOTAL_GROUPS)      // 4

// fp16 copies of V and U (zero-initialized at load; pad columns 150..159 never
// written -> contribute nothing to the dots).
__device__ __half2       g_Vh[VOCAB * ROW_H2];
__device__ __half2       g_Uh[VOCAB * ROW_H2];
__device__ float         g_partials[NBLOCKS];
__device__ unsigned int  g_count = 0;               // self-resets each run

// ---------------- Pass 1: fp32 -> fp16 conversion (vectorized) ----------------
// One thread handles one float4 (4 floats -> 2 half2 stored as uint2).
__global__ void glove_conv_kernel(const float* __restrict__ V,
                                  const float* __restrict__ U) {
    const int F4_PER_ROW = EMBED / 4;               // 75
    const int PER = VOCAB * F4_PER_ROW;             // 750k per matrix
    int t = blockIdx.x * blockDim.x + threadIdx.x;
    const float* src;
    __half2* dstbase;
    int s;
    if (t < PER)            { src = V; dstbase = g_Vh; s = t; }
    else if (t < 2 * PER)   { src = U; dstbase = g_Uh; s = t - PER; }
    else return;

    int row = s / F4_PER_ROW;
    int c   = s - row * F4_PER_ROW;
    float4 f = ((const float4*)(src + (size_t)row * EMBED))[c];
    __half2 h0 = __floats2half2_rn(f.x, f.y);
    __half2 h1 = __floats2half2_rn(f.z, f.w);
    __half2* d = dstbase + (size_t)row * ROW_H2 + 2 * c;
    uint2 packed;
    packed.x = *(unsigned int*)&h0;
    packed.y = *(unsigned int*)&h1;
    *(uint2*)d = packed;
}

// ---------------- Pass 2: fused gather + dot + loss + reduce ----------------
__device__ __forceinline__ float2 dot_fold(uint4 a, uint4 b, float2 acc) {
    const __half2* ah = (const __half2*)&a;
    const __half2* bh = (const __half2*)&b;
    __half2 p = __hmul2(ah[0], bh[0]);
    p = __hfma2(ah[1], bh[1], p);
    p = __hfma2(ah[2], bh[2], p);
    p = __hfma2(ah[3], bh[3], p);
    float2 f = __half22float2(p);
    acc.x += f.x;
    acc.y += f.y;
    return acc;
}

__global__ void __launch_bounds__(NTHREADS)
glove_main_kernel(const int* __restrict__ ci,
                  const int* __restrict__ cj,
                  const float* __restrict__ vb,
                  const float* __restrict__ ub,
                  const float* __restrict__ comat,
                  float* __restrict__ out) {
    const int lane = threadIdx.x & 31;
    const int sub  = lane & 7;                      // lane within 8-lane group
    const int wid  = threadIdx.x >> 5;
    const int group = blockIdx.x * GROUPS_PER_BLOCK + (threadIdx.x >> 3);

    // Hoist all 4 pairs' indices (coalesced reads, latency overlapped).
    int iv[PAIRS_PER_GROUP], jv[PAIRS_PER_GROUP];
    #pragma unroll
    for (int q = 0; q < PAIRS_PER_GROUP; q++) {
        iv[q] = ci[group + q * TOTAL_GROUPS];
        jv[q] = cj[group + q * TOTAL_GROUPS];
    }

    float gsum = 0.0f;                              // only sub==0 lanes accumulate

    #pragma unroll
    for (int qq = 0; qq < PAIRS_PER_GROUP / 2; qq++) {
        const int iA = iv[2 * qq],     jA = jv[2 * qq];
        const int iB = iv[2 * qq + 1], jB = jv[2 * qq + 1];

        const uint4* __restrict__ vA = (const uint4*)(g_Vh + (size_t)iA * ROW_H2);
        const uint4* __restrict__ uA = (const uint4*)(g_Uh + (size_t)jA * ROW_H2);
        const uint4* __restrict__ vB = (const uint4*)(g_Vh + (size_t)iB * ROW_H2);
        const uint4* __restrict__ uB = (const uint4*)(g_Uh + (size_t)jB * ROW_H2);

        // 40 uint4 per padded row; 8 lanes x 5 rounds, 2 pairs interleaved.
        float2 accA = make_float2(0.0f, 0.0f);
        float2 accB = make_float2(0.0f, 0.0f);
        #pragma unroll
        for (int k = 0; k < 5; k++) {
            uint4 a0 = vA[sub + k * 8];
            uint4 b0 = uA[sub + k * 8];
            uint4 a1 = vB[sub + k * 8];
            uint4 b1 = uB[sub + k * 8];
            accA = dot_fold(a0, b0, accA);
            accB = dot_fold(a1, b1, accB);
        }
        float dA = accA.x + accA.y;
        float dB = accB.x + accB.y;

        // reduce within the 8-lane group
        dA += __shfl_xor_sync(0xffffffffu, dA, 4);
        dA += __shfl_xor_sync(0xffffffffu, dA, 2);
        dA += __shfl_xor_sync(0xffffffffu, dA, 1);
        dB += __shfl_xor_sync(0xffffffffu, dB, 4);
        dB += __shfl_xor_sync(0xffffffffu, dB, 2);
        dB += __shfl_xor_sync(0xffffffffu, dB, 1);

        if (sub == 0) {
            float xA = __ldg(comat + (size_t)iA * VOCAB + jA);
            float xB = __ldg(comat + (size_t)iB * VOCAB + jB);
            float wA = (xA < 100.0f) ? __powf(xA * 0.01f, 0.75f) : 1.0f;
            float wB = (xB < 100.0f) ? __powf(xB * 0.01f, 0.75f) : 1.0f;
            float rA = dA + __ldg(vb + iA) + __ldg(ub + jA) - __logf(xA);
            float rB = dB + __ldg(vb + iB) + __ldg(ub + jB) - __logf(xB);
            gsum += wA * rA * rA + wB * rB * rB;
        }
    }

    // warp reduce: nonzero only on lanes 0,8,16,24
    gsum += __shfl_xor_sync(0xffffffffu, gsum, 8);
    gsum += __shfl_xor_sync(0xffffffffu, gsum, 16);

    __shared__ float swsum[NTHREADS / 32];
    __shared__ bool  s_last;
    if (lane == 0) swsum[wid] = gsum;
    __syncthreads();

    if (threadIdx.x == 0) {
        float bsum = 0.0f;
        #pragma unroll
        for (int w = 0; w < NTHREADS / 32; w++) bsum += swsum[w];
        g_partials[blockIdx.x] = bsum;
        __threadfence();
        unsigned int t = atomicAdd(&g_count, 1u);
        s_last = (t == (unsigned int)(gridDim.x - 1));
    }
    __syncthreads();

    if (s_last) {
        double d = 0.0;
        for (int k = threadIdx.x; k < NBLOCKS; k += NTHREADS)
            d += (double)g_partials[k];
        #pragma unroll
        for (int off = 16; off; off >>= 1)
            d += __shfl_xor_sync(0xffffffffu, d, off);

        __shared__ double sdw[NTHREADS / 32];
        if (lane == 0) sdw[wid] = d;
        __syncthreads();
        if (threadIdx.x == 0) {
            double total = 0.0;
            #pragma unroll
            for (int w = 0; w < NTHREADS / 32; w++) total += sdw[w];
            out[0] = (float)total;
            g_count = 0;                            // reset for next graph replay
        }
    }
}

extern "C" void kernel_launch(void* const* d_in, const int* in_sizes, int n_in,
                              void* d_out, int out_size) {
    const int*   ci    = (const int*)d_in[0];
    const int*   cj    = (const int*)d_in[1];
    const float* V     = (const float*)d_in[2];
    const float* U     = (const float*)d_in[3];
    const float* vb    = (const float*)d_in[4];
    const float* ub    = (const float*)d_in[5];
    const float* comat = (const float*)d_in[6];
    float* out = (float*)d_out;

    const int conv_items = 2 * VOCAB * (EMBED / 4); // 1.5M float4 conversions
    glove_conv_kernel<<<(conv_items + 255) / 256, 256>>>(V, U);
    glove_main_kernel<<<NBLOCKS, NTHREADS>>>(ci, cj, vb, ub, comat, out);
}